// round 6
// baseline (speedup 1.0000x reference)
#include <cuda_runtime.h>

// Problem constants (fixed by the reference: B=8, N=8192, D=3)
#define BATCH 8
#define NPTS 8192
#define THREADS 128
#define PTS 4                                   // adv points per thread (2 f32x2 packs)
#define PTS_PER_BLOCK (THREADS * PTS)           // 512
#define BLOCKS_PER_BATCH (NPTS / PTS_PER_BLOCK) // 16
#define NBLOCKS (BATCH * BLOCKS_PER_BATCH)      // 128
#define TILE 1024                               // ori points staged in smem per tile

typedef unsigned long long ull;

// Scratch for deterministic two-pass reduction (no device allocation allowed).
__device__ float g_partials[NBLOCKS];

// ---- packed fp32x2 helpers (sm_103a; ptxas never emits FFMA2 from C++) ----
__device__ __forceinline__ ull pack2(float lo, float hi) {
    ull r;
    asm("mov.b64 %0, {%1, %2};" : "=l"(r) : "f"(lo), "f"(hi));
    return r;
}
__device__ __forceinline__ void unpack2(ull v, float& lo, float& hi) {
    asm("mov.b64 {%0, %1}, %2;" : "=f"(lo), "=f"(hi) : "l"(v));
}
__device__ __forceinline__ ull ffma2(ull a, ull b, ull c) {
    ull d;
    asm("fma.rn.f32x2 %0, %1, %2, %3;" : "=l"(d) : "l"(a), "l"(b), "l"(c));
    return d;
}

// Kernel 1: for each adv point a, min over all ori points o of
//   v = c_o - ax*ox - ay*oy - az*oz,  c_o = 0.5*||o||^2
// then d = ||a||^2 + 2*min(v). Inner loop: 6 FFMA2 + 4 FMNMX + 2 LDS.128
// per ori point per thread (4 adv points).
__global__ __launch_bounds__(THREADS, 1)
void chamfer_min_kernel(const float* __restrict__ adv, const float* __restrict__ ori) {
    // Duplicated tile: per ori point 8 floats {x,x, y,y, z,z, c,c} (32 B)
    __shared__ __align__(16) float s_dup[TILE * 8];   // 32 KB
    __shared__ float s_red[THREADS];

    const int blk  = blockIdx.x;
    const int b    = blk / BLOCKS_PER_BATCH;
    const int cblk = blk % BLOCKS_PER_BATCH;
    const int tid  = threadIdx.x;

    const float* __restrict__ advb = adv + (size_t)b * NPTS * 3;
    const float* __restrict__ orib = ori + (size_t)b * NPTS * 3;

    // Load this thread's 4 adv points; negate coords so inner loop is pure FFMA2.
    float ra[PTS];
    float ax[PTS], ay[PTS], az[PTS];
#pragma unroll
    for (int p = 0; p < PTS; p++) {
        const int j = cblk * PTS_PER_BLOCK + p * THREADS + tid;
        const float x = advb[j * 3 + 0];
        const float y = advb[j * 3 + 1];
        const float z = advb[j * 3 + 2];
        ra[p] = x * x + y * y + z * z;
        ax[p] = -x; ay[p] = -y; az[p] = -z;
    }
    // Two packed pairs: (p0,p1) and (p2,p3)
    const ull nax01 = pack2(ax[0], ax[1]), nay01 = pack2(ay[0], ay[1]), naz01 = pack2(az[0], az[1]);
    const ull nax23 = pack2(ax[2], ax[3]), nay23 = pack2(ay[2], ay[3]), naz23 = pack2(az[2], az[3]);

    float mn0 = __int_as_float(0x7f800000), mn1 = mn0, mn2 = mn0, mn3 = mn0;

    for (int t0 = 0; t0 < NPTS; t0 += TILE) {
        // Stage ori tile, duplicated, with half-squared-norm folded in.
        for (int i = tid; i < TILE; i += THREADS) {
            const float x = orib[(t0 + i) * 3 + 0];
            const float y = orib[(t0 + i) * 3 + 1];
            const float z = orib[(t0 + i) * 3 + 2];
            const float c = 0.5f * (x * x + y * y + z * z);
            float* d = s_dup + i * 8;
            d[0] = x; d[1] = x; d[2] = y; d[3] = y;
            d[4] = z; d[5] = z; d[6] = c; d[7] = c;
        }
        __syncthreads();

        const ulonglong2* __restrict__ sp = (const ulonglong2*)s_dup;
#pragma unroll 8
        for (int i = 0; i < TILE; i++) {
            const ulonglong2 v1 = sp[2 * i];      // {x,x}, {y,y}  (broadcast LDS.128)
            const ulonglong2 v2 = sp[2 * i + 1];  // {z,z}, {c,c}

            ull t01 = ffma2(naz01, v2.x, v2.y);
            ull t23 = ffma2(naz23, v2.x, v2.y);
            t01 = ffma2(nay01, v1.y, t01);
            t23 = ffma2(nay23, v1.y, t23);
            t01 = ffma2(nax01, v1.x, t01);
            t23 = ffma2(nax23, v1.x, t23);

            float a, b2, c2, d2;
            unpack2(t01, a, b2);
            unpack2(t23, c2, d2);
            mn0 = fminf(mn0, a);
            mn1 = fminf(mn1, b2);
            mn2 = fminf(mn2, c2);
            mn3 = fminf(mn3, d2);
        }
        __syncthreads();
    }

    // Per-thread sum of nearest distances, then block reduction.
    float sum = (ra[0] + 2.0f * mn0) + (ra[1] + 2.0f * mn1)
              + (ra[2] + 2.0f * mn2) + (ra[3] + 2.0f * mn3);

    s_red[tid] = sum;
    __syncthreads();
    if (tid < 64) s_red[tid] += s_red[tid + 64];
    __syncthreads();
    if (tid < 32) {
        float v = s_red[tid] + s_red[tid + 32];
#pragma unroll
        for (int o = 16; o > 0; o >>= 1)
            v += __shfl_down_sync(0xffffffffu, v, o);
        if (tid == 0) g_partials[blk] = v;
    }
}

// Kernel 2: weighted mean over the 128 partials (deterministic).
__global__ void chamfer_finalize_kernel(const float* __restrict__ weights,
                                        float* __restrict__ out) {
    __shared__ float s_red[NBLOCKS];
    const int tid = threadIdx.x;   // NBLOCKS threads
    const int b = tid / BLOCKS_PER_BATCH;
    float v = g_partials[tid] * weights[b];
    s_red[tid] = v;
    __syncthreads();
    for (int s2 = NBLOCKS / 2; s2 > 32; s2 >>= 1) {
        if (tid < s2) s_red[tid] += s_red[tid + s2];
        __syncthreads();
    }
    if (tid < 32) {
        float w = s_red[tid] + s_red[tid + 32];
#pragma unroll
        for (int o = 16; o > 0; o >>= 1)
            w += __shfl_down_sync(0xffffffffu, w, o);
        if (tid == 0)
            out[0] = w * (1.0f / ((float)NPTS * (float)BATCH));
    }
}

extern "C" void kernel_launch(void* const* d_in, const int* in_sizes, int n_in,
                              void* d_out, int out_size) {
    const float* adv     = (const float*)d_in[0];  // adv_pc  [B, N, 3]
    const float* ori     = (const float*)d_in[1];  // ori_pc  [B, N, 3]
    const float* weights = (const float*)d_in[2];  // weights [B]
    float* out = (float*)d_out;                    // scalar

    chamfer_min_kernel<<<NBLOCKS, THREADS>>>(adv, ori);
    chamfer_finalize_kernel<<<1, NBLOCKS>>>(weights, out);
}